// round 6
// baseline (speedup 1.0000x reference)
#include <cuda_runtime.h>
#include <cuda_fp16.h>
#include <math.h>
#include <stdint.h>

typedef __half fp16;

#define BATCH 8192
#define PDIM  512
#define H1DIM 1024
#define H2DIM 512
#define NOUTD 1024
#define MMDIM 512
#define NCODE 2048
#define KSTEPS 16

// ---------------- device scratch (no allocations allowed) -------------------
__device__ float g_v [(size_t)BATCH * NCODE];   // FISTA v (fp32)
__device__ float g_a0[(size_t)BATCH * NCODE];   // alpha (fp32)

__device__ fp16 g_xsh[(size_t)BATCH*PDIM],  g_xsl[(size_t)BATCH*PDIM];
__device__ fp16 g_h1h[(size_t)BATCH*H1DIM], g_h1l[(size_t)BATCH*H1DIM];
__device__ fp16 g_h2h[(size_t)BATCH*H2DIM], g_h2l[(size_t)BATCH*H2DIM];
__device__ fp16 g_ybh[(size_t)BATCH*NOUTD], g_ybl[(size_t)BATCH*NOUTD];
__device__ fp16 g_vh [(size_t)BATCH*NCODE], g_vl [(size_t)BATCH*NCODE];
__device__ fp16 g_rh [(size_t)BATCH*MMDIM], g_rl [(size_t)BATCH*MMDIM];
__device__ fp16 g_aph[(size_t)BATCH*NCODE], g_apl[(size_t)BATCH*NCODE];

__device__ fp16 g_w1[(size_t)H1DIM*PDIM];    // W1^T
__device__ fp16 g_w2[(size_t)H2DIM*H1DIM];   // W2^T
__device__ fp16 g_w3[(size_t)NOUTD*H2DIM];   // W3^T
__device__ fp16 g_m [(size_t)MMDIM*NOUTD];   // M
__device__ fp16 g_aa[(size_t)MMDIM*NCODE];   // A
__device__ fp16 g_at[(size_t)NCODE*MMDIM];   // A^T
__device__ fp16 g_ps[(size_t)NOUTD*NCODE];   // Psi

// ---------------- dependency counters ----------------------------------------
#define C_MLP1 0
#define C_MLP2 64
#define C_MLP3 128
#define C_Z    192
#define C_R    256            // + k*64 + m   (target 4)
#define C_A    (256 + 1024)   // + k*64 + m   (target 16)
#define NCNT   (256 + 2048)
__device__ int g_cnt[NCNT];

// ---------------- tile segment layout (bid order = dependency order) ---------
#define BID_MLP2 512
#define BID_MLP3 768
#define BID_Z    1280
#define BID_LOOP 1536
#define NT_STEP  1280              // 256 r-tiles + 1024 alpha-tiles
#define BID_YHAT (BID_LOOP + KSTEPS * NT_STEP)   // 22016
#define NBLK     (BID_YHAT + 512)                // 22528

// ---------------- PTX helpers -------------------------------------------------
__device__ __forceinline__ uint32_t smem_u32(const void* p) {
    uint32_t a;
    asm("{ .reg .u64 t; cvta.to.shared.u64 t, %1; cvt.u32.u64 %0, t; }" : "=r"(a) : "l"(p));
    return a;
}
__device__ __forceinline__ void cp16(uint32_t d, const void* s) {
    asm volatile("cp.async.cg.shared.global [%0], [%1], 16;" :: "r"(d), "l"(s) : "memory");
}
#define CP_COMMIT() asm volatile("cp.async.commit_group;" ::: "memory")
#define CP_WAIT0()  asm volatile("cp.async.wait_group 0;" ::: "memory")
#define CP_WAIT1()  asm volatile("cp.async.wait_group 1;" ::: "memory")

#define LDSM4(r0, r1, r2, r3, a) \
    asm volatile("ldmatrix.sync.aligned.m8n8.x4.shared.b16 {%0,%1,%2,%3}, [%4];" \
                 : "=r"(r0), "=r"(r1), "=r"(r2), "=r"(r3) : "r"(a))

#define MMA16816(c, a, b) \
    asm volatile("mma.sync.aligned.m16n8k16.row.col.f32.f16.f16.f32 " \
                 "{%0,%1,%2,%3}, {%4,%5,%6,%7}, {%8,%9}, {%0,%1,%2,%3};" \
                 : "+f"((c)[0]), "+f"((c)[1]), "+f"((c)[2]), "+f"((c)[3]) \
                 : "r"((a)[0]), "r"((a)[1]), "r"((a)[2]), "r"((a)[3]), \
                   "r"((b)[0]), "r"((b)[1]))

// CTA-level dependency wait / signal (L2-coherent; producers have lower bids,
// so they are dispatched first -> no livelock under in-order work distribution)
__device__ __forceinline__ void ctawait(const int* p, int tgt) {
    if (threadIdx.x == 0) {
        const volatile int* vp = (const volatile int*)p;
        while (*vp < tgt) __nanosleep(64);
        __threadfence();
    }
    __syncthreads();
}
__device__ __forceinline__ void ctasignal(int* p) {
    __syncthreads();
    if (threadIdx.x == 0) {
        __threadfence();
        atomicAdd(p, 1);
    }
}

// ---------------- GEMM constants ----------------------------------------------
#define ROW_B   144
#define TILE_B  (128 * ROW_B)
#define STAGE_B (3 * TILE_B)             // Ah, Al, B = 55296 B
#define SMEM_BYTES (3 * STAGE_B)         // 165888 B

enum { EPI_GELU = 0, EPI_YBG, EPI_ZSUB, EPI_RSUB, EPI_FISTA, EPI_ADD };

__device__ __forceinline__ float gelu_exact(float x) {
    return 0.5f * x * (1.0f + erff(x * 0.70710678118654752440f));
}
__device__ __forceinline__ void split2h(fp16* H, fp16* L, size_t idx, float o0, float o1) {
    fp16 h0 = __float2half_rn(o0), h1 = __float2half_rn(o1);
    fp16 l0 = __float2half_rn(o0 - __half2float(h0));
    fp16 l1 = __float2half_rn(o1 - __half2float(h1));
    *(__half2*)(H + idx) = __halves2half2(h0, h1);
    *(__half2*)(L + idx) = __halves2half2(l0, l1);
}

// ---------------------------------------------------------------------------
// MEGA kernel: the whole computation graph as one launch.
// ---------------------------------------------------------------------------
__global__ void __launch_bounds__(256, 1)
mega(fp16* __restrict__ xsh, fp16* __restrict__ xsl,
     fp16* __restrict__ h1h, fp16* __restrict__ h1l,
     fp16* __restrict__ h2h, fp16* __restrict__ h2l,
     fp16* __restrict__ ybh, fp16* __restrict__ ybl,
     fp16* __restrict__ vh,  fp16* __restrict__ vl,
     fp16* __restrict__ rh,  fp16* __restrict__ rl,
     fp16* __restrict__ aph, fp16* __restrict__ apl,
     const fp16* __restrict__ w1, const fp16* __restrict__ w2,
     const fp16* __restrict__ w3, const fp16* __restrict__ mw,
     const fp16* __restrict__ aa, const fp16* __restrict__ at,
     const fp16* __restrict__ ps,
     float* __restrict__ vbuf, float* __restrict__ abuf,
     float* __restrict__ o_ybg, float* __restrict__ o_z,
     float* __restrict__ o_alpha, float* __restrict__ o_yhat,
     const float* __restrict__ b1, const float* __restrict__ b2,
     const float* __restrict__ b3, const float* __restrict__ bvec,
     const float* __restrict__ leta, const float* __restrict__ ltau,
     int* __restrict__ cnt)
{
    extern __shared__ char dyn[];
    const uint32_t sbase = smem_u32(dyn);

    const int bid = blockIdx.x;
    const int tid = threadIdx.x;
    const int wid = tid >> 5;
    const int lid = tid & 31;

    // ---------------- decode tile ------------------------------------------------
    int epi, kstep = 0, mt, nt, Kdim, Ndim;
    const fp16 *Ah = nullptr, *Al = nullptr, *Bw = nullptr;
    fp16 *Ch = nullptr, *Cl = nullptr;
    float *C0 = nullptr, *vout = nullptr;
    fp16 *vho = nullptr, *vlo = nullptr;
    const float *aux = nullptr, *aux2 = nullptr;
    const int* waitc = nullptr; int waittgt = 0;
    int* sigc = nullptr;
    bool copyz = false;

    if (bid < BID_MLP2) {                       // MLP1: h1 = gelu(x@W1+b1)
        int t = bid; mt = t >> 3; nt = t & 7;
        epi = EPI_GELU; Kdim = PDIM; Ndim = H1DIM;
        Ah = xsh; Al = xsl; Bw = w1; Ch = h1h; Cl = h1l; aux = b1;
        sigc = &cnt[C_MLP1 + mt];
    } else if (bid < BID_MLP3) {                // MLP2
        int t = bid - BID_MLP2; mt = t >> 2; nt = t & 3;
        epi = EPI_GELU; Kdim = H1DIM; Ndim = H2DIM;
        Ah = h1h; Al = h1l; Bw = w2; Ch = h2h; Cl = h2l; aux = b2;
        waitc = &cnt[C_MLP1 + mt]; waittgt = 8; sigc = &cnt[C_MLP2 + mt];
    } else if (bid < BID_Z) {                   // MLP3: ybg
        int t = bid - BID_MLP3; mt = t >> 3; nt = t & 7;
        epi = EPI_YBG; Kdim = H2DIM; Ndim = NOUTD;
        Ah = h2h; Al = h2l; Bw = w3; C0 = o_ybg; Ch = ybh; Cl = ybl; aux = b3;
        waitc = &cnt[C_MLP2 + mt]; waittgt = 4; sigc = &cnt[C_MLP3 + mt];
    } else if (bid < BID_LOOP) {                // z = b - ybg@M^T
        int t = bid - BID_Z; mt = t >> 2; nt = t & 3;
        epi = EPI_ZSUB; Kdim = NOUTD; Ndim = MMDIM;
        Ah = ybh; Al = ybl; Bw = mw; C0 = o_z; aux = bvec;
        waitc = &cnt[C_MLP3 + mt]; waittgt = 8; sigc = &cnt[C_Z + mt];
    } else if (bid < BID_YHAT) {                // FISTA loop
        int t = bid - BID_LOOP;
        int k = t / NT_STEP, u = t % NT_STEP;
        kstep = k;
        if (u < 256) {                          // r tile
            mt = u >> 2; nt = u & 3; Ndim = MMDIM;
            if (k == 0) {
                copyz = true;
                waitc = &cnt[C_Z + mt]; waittgt = 4;
            } else {
                epi = EPI_RSUB; Kdim = NCODE;
                Ah = vh; Al = vl; Bw = aa; Ch = rh; Cl = rl; aux = o_z;
                waitc = &cnt[C_A + (k - 1) * 64 + mt]; waittgt = 16;
            }
            sigc = &cnt[C_R + k * 64 + mt];
        } else {                                // alpha tile
            int u2 = u - 256; mt = u2 >> 4; nt = u2 & 15;
            epi = EPI_FISTA; Kdim = MMDIM; Ndim = NCODE;
            Ah = rh; Al = rl; Bw = at; aux = vbuf; aux2 = abuf;
            if (k < KSTEPS - 1) { C0 = abuf; vout = vbuf; vho = vh; vlo = vl; }
            else                { C0 = o_alpha; Ch = aph; Cl = apl; }
            waitc = &cnt[C_R + k * 64 + mt]; waittgt = 4;
            sigc = &cnt[C_A + k * 64 + mt];
        }
    } else {                                    // yhat = ybg + alpha@Psi^T
        int t = bid - BID_YHAT; mt = t >> 3; nt = t & 7;
        epi = EPI_ADD; Kdim = NCODE; Ndim = NOUTD;
        Ah = aph; Al = apl; Bw = ps; C0 = o_yhat; aux = o_ybg;
        waitc = &cnt[C_A + (KSTEPS - 1) * 64 + mt]; waittgt = 16;
    }

    const int m0 = mt * 128;
    const int n0 = nt * 128;

    if (waitc) ctawait(waitc, waittgt);

    // ---------------- step-0 r tile: r = -z (copy + split) -----------------------
    if (copyz) {
#pragma unroll 4
        for (int i = 0; i < 32; i++) {
            int e = tid + i * 256;              // 8192 float2 elems
            int row = e >> 6, cp = e & 63;
            size_t idx = (size_t)(m0 + row) * MMDIM + n0 + cp * 2;
            float2 zv = __ldcg((const float2*)&o_z[idx]);
            split2h(rh, rl, idx, -zv.x, -zv.y);
        }
        if (sigc) ctasignal(sigc);
        return;
    }

    // ---------------- GEMM mainloop ----------------------------------------------
    const int m_w = (wid >> 2) * 64;
    const int n_w = (wid & 3) * 32;

    const fp16* gp[12];
    uint32_t so[12];
    {
        const fp16* srcs[3] = { Ah, Al, Bw };
#pragma unroll
        for (int it = 0; it < 12; it++) {
            const int op  = it >> 2;
            const int row = (it & 3) * 32 + (tid >> 3);
            const int seg = tid & 7;
            const int rb  = (op < 2) ? m0 : n0;
            gp[it] = srcs[op] + (size_t)(rb + row) * Kdim + seg * 8;
            so[it] = (uint32_t)(op * TILE_B + row * ROW_B + seg * 16);
        }
    }

    const int aRow = (lid & 7) + ((lid >> 3) & 1) * 8;
    const int aK   = ((lid >> 4) & 1) * 8;
    const int bRow = (lid & 7) + ((lid >> 4) & 1) * 8;
    const int bK   = ((lid >> 3) & 1) * 8;
    const uint32_t aOff = (uint32_t)((m_w + aRow) * ROW_B + aK * 2);
    const uint32_t bOff = (uint32_t)((n_w + bRow) * ROW_B + bK * 2);

    float acc[4][4][4];
#pragma unroll
    for (int i = 0; i < 4; i++)
#pragma unroll
        for (int j = 0; j < 4; j++)
#pragma unroll
            for (int c = 0; c < 4; c++) acc[i][j][c] = 0.0f;

    const int S = Kdim >> 6;

#pragma unroll
    for (int it = 0; it < 12; it++) cp16(sbase + so[it], gp[it]);
    CP_COMMIT();
#pragma unroll
    for (int it = 0; it < 12; it++) cp16(sbase + STAGE_B + so[it], gp[it] + 64);
    CP_COMMIT();

    int cb = 0, pb = 2;
    for (int s = 0; s < S; s++) {
        if (s + 2 < S) { CP_WAIT1(); } else { CP_WAIT0(); }
        __syncthreads();
        if (s + 2 < S) {
            const uint32_t db = sbase + (uint32_t)(pb * STAGE_B);
            const int k0 = (s + 2) * 64;
#pragma unroll
            for (int it = 0; it < 12; it++) cp16(db + so[it], gp[it] + k0);
            CP_COMMIT();
        }
        const uint32_t st = sbase + (uint32_t)(cb * STAGE_B);

#pragma unroll
        for (int kk = 0; kk < 4; kk++) {
            uint32_t ah[4][4], al[4][4], bh[4][2];
#pragma unroll
            for (int i = 0; i < 4; i++) {
                LDSM4(ah[i][0], ah[i][1], ah[i][2], ah[i][3],
                      st + aOff + i * (16 * ROW_B) + kk * 32);
                LDSM4(al[i][0], al[i][1], al[i][2], al[i][3],
                      st + TILE_B + aOff + i * (16 * ROW_B) + kk * 32);
            }
#pragma unroll
            for (int j = 0; j < 2; j++) {
                uint32_t r0, r1, r2, r3;
                LDSM4(r0, r1, r2, r3,
                      st + 2 * TILE_B + bOff + j * (16 * ROW_B) + kk * 32);
                bh[2 * j][0] = r0; bh[2 * j][1] = r1;
                bh[2 * j + 1][0] = r2; bh[2 * j + 1][1] = r3;
            }
#pragma unroll
            for (int i = 0; i < 4; i++)
#pragma unroll
                for (int j = 0; j < 4; j++) {
                    MMA16816(acc[i][j], ah[i], bh[j]);
                    MMA16816(acc[i][j], al[i], bh[j]);
                }
        }
        cb = (cb == 2) ? 0 : cb + 1;
        pb = (pb == 2) ? 0 : pb + 1;
    }

    // ---------------- fused epilogue ----------------------------------------------
    float eta = 0.0f, thr = 0.0f, beta = 0.0f;
    if (epi == EPI_FISTA) {
        eta = expf(leta[kstep]);  eta = fminf(fmaxf(eta, 1e-8f), 10.0f);
        float tau = expf(ltau[kstep]); tau = fminf(fmaxf(tau, 1e-8f), 10.0f);
        thr = eta * tau;
        float t = 1.0f;                 // beta_{k+1} for v-momentum fusion
        for (int i = 1; i <= kstep + 1; i++) {
            float tn = 0.5f * (1.0f + sqrtf(1.0f + 4.0f * t * t));
            beta = (t - 1.0f) / tn;
            t = tn;
        }
    }
    const bool k0f  = (epi == EPI_FISTA) && (kstep == 0);
    const bool last = (epi == EPI_FISTA) && (kstep == KSTEPS - 1);

#pragma unroll
    for (int i = 0; i < 4; i++) {
#pragma unroll
        for (int j = 0; j < 4; j++) {
#pragma unroll
            for (int half = 0; half < 2; half++) {
                const int row = m0 + m_w + i * 16 + (lid >> 2) + half * 8;
                const int col = n0 + n_w + j * 8 + (lid & 3) * 2;
                const size_t idx = (size_t)row * Ndim + col;
                float o0 = acc[i][j][half * 2];
                float o1 = acc[i][j][half * 2 + 1];

                if (epi == EPI_GELU) {
                    float2 bv = *(const float2*)&aux[col];
                    o0 = gelu_exact(o0 + bv.x);
                    o1 = gelu_exact(o1 + bv.y);
                    split2h(Ch, Cl, idx, o0, o1);
                } else if (epi == EPI_YBG) {
                    float2 bv = *(const float2*)&aux[col];
                    o0 += bv.x; o1 += bv.y;
                    *(float2*)&C0[idx] = make_float2(o0, o1);
                    split2h(Ch, Cl, idx, o0, o1);
                } else if (epi == EPI_ZSUB) {
                    float2 av = *(const float2*)&aux[idx];     // bvec (input)
                    *(float2*)&C0[idx] = make_float2(av.x - o0, av.y - o1);
                } else if (epi == EPI_RSUB) {
                    float2 av = __ldcg((const float2*)&aux[idx]);  // o_z (in-launch)
                    o0 -= av.x; o1 -= av.y;
                    split2h(Ch, Cl, idx, o0, o1);
                } else if (epi == EPI_FISTA) {
                    float2 vv = k0f ? make_float2(0.f, 0.f)
                                    : __ldcg((const float2*)&aux[idx]);   // v
                    float u0 = vv.x - eta * o0, u1 = vv.y - eta * o1;
                    float a0n = copysignf(fmaxf(fabsf(u0) - thr, 0.0f), u0);
                    float a1n = copysignf(fmaxf(fabsf(u1) - thr, 0.0f), u1);
                    if (!last) {
                        float2 ao = k0f ? make_float2(0.f, 0.f)
                                        : __ldcg((const float2*)&aux2[idx]);  // alpha_old
                        float v0 = a0n + beta * (a0n - ao.x);
                        float v1 = a1n + beta * (a1n - ao.y);
                        *(float2*)&C0[idx]   = make_float2(a0n, a1n);
                        *(float2*)&vout[idx] = make_float2(v0, v1);
                        split2h(vho, vlo, idx, v0, v1);
                    } else {
                        *(float2*)&C0[idx] = make_float2(a0n, a1n);
                        split2h(Ch, Cl, idx, a0n, a1n);
                    }
                } else {                                       // EPI_ADD
                    float2 yv = __ldcg((const float2*)&aux[idx]);  // o_ybg (in-launch)
                    *(float2*)&C0[idx] = make_float2(o0 + yv.x, o1 + yv.y);
                }
            }
        }
    }

    if (sigc) ctasignal(sigc);
}

// ---------------- prep kernels ------------------------------------------------
__global__ void split_kernel(const float4* __restrict__ s, fp16* __restrict__ h,
                             fp16* __restrict__ l, int n4)
{
    int i = blockIdx.x * blockDim.x + threadIdx.x;
    if (i < n4) {
        float4 v = s[i];
        size_t idx = (size_t)i * 4;
        fp16 h0 = __float2half_rn(v.x), h1 = __float2half_rn(v.y);
        fp16 h2 = __float2half_rn(v.z), h3 = __float2half_rn(v.w);
        *(__half2*)(h + idx)     = __halves2half2(h0, h1);
        *(__half2*)(h + idx + 2) = __halves2half2(h2, h3);
        fp16 l0 = __float2half_rn(v.x - __half2float(h0));
        fp16 l1 = __float2half_rn(v.y - __half2float(h1));
        fp16 l2 = __float2half_rn(v.z - __half2float(h2));
        fp16 l3 = __float2half_rn(v.w - __half2float(h3));
        *(__half2*)(l + idx)     = __halves2half2(l0, l1);
        *(__half2*)(l + idx + 2) = __halves2half2(l2, l3);
    }
}

__global__ void round_kernel(const float4* __restrict__ s, fp16* __restrict__ o, int n4)
{
    int i = blockIdx.x * blockDim.x + threadIdx.x;
    if (i < n4) {
        float4 v = s[i];
        size_t idx = (size_t)i * 4;
        *(__half2*)(o + idx)     = __halves2half2(__float2half_rn(v.x), __float2half_rn(v.y));
        *(__half2*)(o + idx + 2) = __halves2half2(__float2half_rn(v.z), __float2half_rn(v.w));
    }
}

__global__ void tround_kernel(const float* __restrict__ s, fp16* __restrict__ o,
                              int R, int C)
{
    __shared__ float t[32][33];
    const int bx = blockIdx.x * 32;
    const int by = blockIdx.y * 32;
    const int x = threadIdx.x, y = threadIdx.y;
#pragma unroll
    for (int i = 0; i < 4; i++)
        t[y + i * 8][x] = s[(size_t)(by + y + i * 8) * C + bx + x];
    __syncthreads();
#pragma unroll
    for (int i = 0; i < 4; i++)
        o[(size_t)(bx + y + i * 8) * R + by + x] = __float2half_rn(t[x][y + i * 8]);
}

__global__ void zcnt_kernel(int* __restrict__ c, int n)
{
    int i = blockIdx.x * blockDim.x + threadIdx.x;
    if (i < n) c[i] = 0;
}

// ---------------------------------------------------------------------------
extern "C" void kernel_launch(void* const* d_in, const int* in_sizes, int n_in,
                              void* d_out, int out_size)
{
    const float* x    = (const float*)d_in[0];
    const float* bvec = (const float*)d_in[1];
    const float* W1   = (const float*)d_in[2];
    const float* b1   = (const float*)d_in[3];
    const float* W2   = (const float*)d_in[4];
    const float* b2   = (const float*)d_in[5];
    const float* W3   = (const float*)d_in[6];
    const float* b3   = (const float*)d_in[7];
    const float* A    = (const float*)d_in[8];
    const float* leta = (const float*)d_in[9];
    const float* ltau = (const float*)d_in[10];
    const float* Psi  = (const float*)d_in[11];
    const float* Mmat = (const float*)d_in[12];

    float* out     = (float*)d_out;
    float* o_ybg   = out;
    float* o_z     = o_ybg   + (size_t)BATCH * NOUTD;
    float* o_alpha = o_z     + (size_t)BATCH * MMDIM;
    float* o_yhat  = o_alpha + (size_t)BATCH * NCODE;

#define SYM(p, s) void* p##_; cudaGetSymbolAddress(&p##_, s); auto* p = (decltype(&s[0]))p##_
    SYM(vbuf, g_v);  SYM(abuf, g_a0);
    SYM(xsh, g_xsh); SYM(xsl, g_xsl);
    SYM(h1h, g_h1h); SYM(h1l, g_h1l);
    SYM(h2h, g_h2h); SYM(h2l, g_h2l);
    SYM(ybh, g_ybh); SYM(ybl, g_ybl);
    SYM(vh, g_vh);   SYM(vl, g_vl);
    SYM(rh, g_rh);   SYM(rl, g_rl);
    SYM(aph, g_aph); SYM(apl, g_apl);
    SYM(w1, g_w1);   SYM(w2, g_w2);   SYM(w3, g_w3);
    SYM(mw, g_m);    SYM(aa, g_aa);   SYM(at, g_at);   SYM(ps, g_ps);
    SYM(cnt, g_cnt);
#undef SYM

    cudaFuncSetAttribute((void*)mega, cudaFuncAttributeMaxDynamicSharedMemorySize, SMEM_BYTES);

    // ---- prep -----------------------------------------------------------------
    {
        int n4 = (BATCH * PDIM) / 4;
        split_kernel<<<(n4 + 255) / 256, 256>>>((const float4*)x, xsh, xsl, n4);
    }
    auto rounds = [&](const float* s, fp16* o, size_t n) {
        int n4 = (int)(n / 4);
        round_kernel<<<(n4 + 255) / 256, 256>>>((const float4*)s, o, n4);
    };
    rounds(A,    aa, (size_t)MMDIM * NCODE);
    rounds(Mmat, mw, (size_t)MMDIM * NOUTD);
    rounds(Psi,  ps, (size_t)NOUTD * NCODE);
    tround_kernel<<<dim3(H1DIM / 32, PDIM / 32),  dim3(32, 8)>>>(W1, w1, PDIM,  H1DIM);
    tround_kernel<<<dim3(H2DIM / 32, H1DIM / 32), dim3(32, 8)>>>(W2, w2, H1DIM, H2DIM);
    tround_kernel<<<dim3(NOUTD / 32, H2DIM / 32), dim3(32, 8)>>>(W3, w3, H2DIM, NOUTD);
    tround_kernel<<<dim3(NCODE / 32, MMDIM / 32), dim3(32, 8)>>>(A,  at, MMDIM, NCODE);
    zcnt_kernel<<<(NCNT + 255) / 256, 256>>>(cnt, NCNT);

    // ---- the whole graph in one launch -----------------------------------------
    mega<<<NBLK, 256, SMEM_BYTES>>>(
        xsh, xsl, h1h, h1l, h2h, h2l, ybh, ybl, vh, vl, rh, rl, aph, apl,
        w1, w2, w3, mw, aa, at, ps,
        vbuf, abuf, o_ybg, o_z, o_alpha, o_yhat,
        b1, b2, b3, bvec, leta, ltau, cnt);
}

// round 7
// speedup vs baseline: 1.9693x; 1.9693x over previous
#include <cuda_runtime.h>
#include <cuda_fp16.h>
#include <math.h>
#include <stdint.h>

typedef __half fp16;

#define BATCH 8192
#define PDIM  512
#define H1DIM 1024
#define H2DIM 512
#define NOUTD 1024
#define MMDIM 512
#define NCODE 2048
#define KSTEPS 16

// ---------------- device scratch (no allocations allowed) -------------------
__device__ float g_v [(size_t)BATCH * NCODE];   // FISTA v (fp32, epilogue aux)
__device__ float g_a0[(size_t)BATCH * NCODE];   // alpha (fp32, epilogue aux2)

// activations: single fp16
__device__ fp16 g_xs[(size_t)BATCH*PDIM];
__device__ fp16 g_h1[(size_t)BATCH*H1DIM];
__device__ fp16 g_h2[(size_t)BATCH*H2DIM];
__device__ fp16 g_yb[(size_t)BATCH*NOUTD];
__device__ fp16 g_vs[(size_t)BATCH*NCODE];
__device__ fp16 g_rs[(size_t)BATCH*MMDIM];
__device__ fp16 g_ap[(size_t)BATCH*NCODE];

// weights / operators: single fp16 (rounded once)
__device__ fp16 g_w1[(size_t)H1DIM*PDIM];    // W1^T
__device__ fp16 g_w2[(size_t)H2DIM*H1DIM];   // W2^T
__device__ fp16 g_w3[(size_t)NOUTD*H2DIM];   // W3^T
__device__ fp16 g_m [(size_t)MMDIM*NOUTD];   // M  (as stored)
__device__ fp16 g_aa[(size_t)MMDIM*NCODE];   // A  (as stored)
__device__ fp16 g_at[(size_t)NCODE*MMDIM];   // A^T
__device__ fp16 g_ps[(size_t)NOUTD*NCODE];   // Psi (as stored)

// ---------------- PTX helpers (legal on base compute_103 target) ------------
__device__ __forceinline__ uint32_t smem_u32(const void* p) {
    uint32_t a;
    asm("{ .reg .u64 t; cvta.to.shared.u64 t, %1; cvt.u32.u64 %0, t; }" : "=r"(a) : "l"(p));
    return a;
}
__device__ __forceinline__ void cp16(uint32_t d, const void* s) {
    asm volatile("cp.async.cg.shared.global [%0], [%1], 16;" :: "r"(d), "l"(s) : "memory");
}
#define CP_COMMIT() asm volatile("cp.async.commit_group;" ::: "memory")
#define CP_WAIT0()  asm volatile("cp.async.wait_group 0;" ::: "memory")
#define CP_WAIT1()  asm volatile("cp.async.wait_group 1;" ::: "memory")

#define LDSM4(r0, r1, r2, r3, a) \
    asm volatile("ldmatrix.sync.aligned.m8n8.x4.shared.b16 {%0,%1,%2,%3}, [%4];" \
                 : "=r"(r0), "=r"(r1), "=r"(r2), "=r"(r3) : "r"(a))

#define MMA16816(c, a, b) \
    asm volatile("mma.sync.aligned.m16n8k16.row.col.f32.f16.f16.f32 " \
                 "{%0,%1,%2,%3}, {%4,%5,%6,%7}, {%8,%9}, {%0,%1,%2,%3};" \
                 : "+f"((c)[0]), "+f"((c)[1]), "+f"((c)[2]), "+f"((c)[3]) \
                 : "r"((a)[0]), "r"((a)[1]), "r"((a)[2]), "r"((a)[3]), \
                   "r"((b)[0]), "r"((b)[1]))

// ---------------- GEMM constants ---------------------------------------------
// SMEM tile: 128 rows x 64 fp16, padded row stride 72 fp16 = 144 B
// (9x16B -> conflict-free ldmatrix phases).
#define ROW_B   144
#define TILE_B  (128 * ROW_B)            // 18432 B per operand tile
#define STAGE_B (2 * TILE_B)             // A, B = 36864 B
#define SMEM_BYTES (3 * STAGE_B)         // 3 stages = 110592 B

enum { EPI_GELU = 0, EPI_YBG, EPI_ZSUB, EPI_RSUB, EPI_FISTA, EPI_ADD };

__device__ __forceinline__ float gelu_exact(float x) {
    return 0.5f * x * (1.0f + erff(x * 0.70710678118654752440f));
}
__device__ __forceinline__ void store2h(fp16* H, size_t idx, float o0, float o1) {
    *(__half2*)(H + idx) = __halves2half2(__float2half_rn(o0), __float2half_rn(o1));
}

// ---------------------------------------------------------------------------
// Warp-MMA GEMM: D[128x128 tile] = A[M,K] * (B[N,K])^T, fp32 acc, single fp16
// product, 3-stage cp.async pipeline, fused epilogue.
// ---------------------------------------------------------------------------
template <int EPI>
__global__ void __launch_bounds__(256, 1)
wgemm(const fp16* __restrict__ Ag, const fp16* __restrict__ Bg,
      int Ndim, int Kdim,
      float* __restrict__ C0, fp16* __restrict__ Ch,
      const float* __restrict__ aux, const float* __restrict__ aux2,
      float* __restrict__ vout, fp16* __restrict__ vho,
      const float* __restrict__ leta, const float* __restrict__ ltau,
      int kidx, float beta)
{
    extern __shared__ char dyn[];
    const uint32_t sbase = smem_u32(dyn);

    const int tid = threadIdx.x;
    const int wid = tid >> 5;
    const int lid = tid & 31;
    const int m0  = blockIdx.y * 128;
    const int n0  = blockIdx.x * 128;
    const int m_w = (wid >> 2) * 64;     // warp m offset
    const int n_w = (wid & 3) * 32;      // warp n offset

    // ---- loader plan: 8 cp.async x 16B per thread per stage ------------------
    const fp16* gp[8];
    uint32_t so[8];
    {
        const fp16* srcs[2] = { Ag, Bg };
#pragma unroll
        for (int it = 0; it < 8; it++) {
            const int op  = it >> 2;                    // 0:A 1:B
            const int row = (it & 3) * 32 + (tid >> 3);
            const int seg = tid & 7;                    // 8 fp16 per 16B
            const int rb  = (op == 0) ? m0 : n0;
            gp[it] = srcs[op] + (size_t)(rb + row) * Kdim + seg * 8;
            so[it] = (uint32_t)(op * TILE_B + row * ROW_B + seg * 16);
        }
    }

    // ---- ldmatrix per-lane offsets -------------------------------------------
    const int aRow = (lid & 7) + ((lid >> 3) & 1) * 8;
    const int aK   = ((lid >> 4) & 1) * 8;
    const int bRow = (lid & 7) + ((lid >> 4) & 1) * 8;
    const int bK   = ((lid >> 3) & 1) * 8;
    const uint32_t aOff = (uint32_t)((m_w + aRow) * ROW_B + aK * 2);
    const uint32_t bOff = (uint32_t)((n_w + bRow) * ROW_B + bK * 2);

    float acc[4][4][4];
#pragma unroll
    for (int i = 0; i < 4; i++)
#pragma unroll
        for (int j = 0; j < 4; j++)
#pragma unroll
            for (int c = 0; c < 4; c++) acc[i][j][c] = 0.0f;

    const int S = Kdim >> 6;   // K-chunks of 64

    // prologue: stages 0,1 -> bufs 0,1
#pragma unroll
    for (int it = 0; it < 8; it++) cp16(sbase + so[it], gp[it]);
    CP_COMMIT();
    if (S > 1) {
#pragma unroll
        for (int it = 0; it < 8; it++) cp16(sbase + STAGE_B + so[it], gp[it] + 64);
        CP_COMMIT();
    }

    int cb = 0, pb = 2;   // compute buf, prefetch buf
    for (int s = 0; s < S; s++) {
        if (s + 2 < S) { CP_WAIT1(); } else { CP_WAIT0(); }
        __syncthreads();
        if (s + 2 < S) {
            const uint32_t db = sbase + (uint32_t)(pb * STAGE_B);
            const int k0 = (s + 2) * 64;
#pragma unroll
            for (int it = 0; it < 8; it++) cp16(db + so[it], gp[it] + k0);
            CP_COMMIT();
        }
        const uint32_t st = sbase + (uint32_t)(cb * STAGE_B);

#pragma unroll
        for (int kk = 0; kk < 4; kk++) {
            uint32_t ah[4][4], bh[4][2];
#pragma unroll
            for (int i = 0; i < 4; i++) {
                LDSM4(ah[i][0], ah[i][1], ah[i][2], ah[i][3],
                      st + aOff + i * (16 * ROW_B) + kk * 32);
            }
#pragma unroll
            for (int j = 0; j < 2; j++) {
                uint32_t r0, r1, r2, r3;
                LDSM4(r0, r1, r2, r3,
                      st + TILE_B + bOff + j * (16 * ROW_B) + kk * 32);
                bh[2 * j][0] = r0; bh[2 * j][1] = r1;
                bh[2 * j + 1][0] = r2; bh[2 * j + 1][1] = r3;
            }
#pragma unroll
            for (int i = 0; i < 4; i++)
#pragma unroll
                for (int j = 0; j < 4; j++)
                    MMA16816(acc[i][j], ah[i], bh[j]);
        }
        cb = (cb == 2) ? 0 : cb + 1;
        pb = (pb == 2) ? 0 : pb + 1;
    }

    // ---- fused epilogue -------------------------------------------------------
    float eta = 0.0f, thr = 0.0f;
    if (EPI == EPI_FISTA) {
        eta = expf(leta[kidx]);  eta = fminf(fmaxf(eta, 1e-8f), 10.0f);
        float tau = expf(ltau[kidx]); tau = fminf(fmaxf(tau, 1e-8f), 10.0f);
        thr = eta * tau;
    }

#pragma unroll
    for (int i = 0; i < 4; i++) {
#pragma unroll
        for (int j = 0; j < 4; j++) {
#pragma unroll
            for (int half = 0; half < 2; half++) {
                const int row = m0 + m_w + i * 16 + (lid >> 2) + half * 8;
                const int col = n0 + n_w + j * 8 + (lid & 3) * 2;
                const size_t idx = (size_t)row * Ndim + col;
                float o0 = acc[i][j][half * 2];
                float o1 = acc[i][j][half * 2 + 1];

                if (EPI == EPI_GELU) {
                    float2 bv = *(const float2*)&aux[col];
                    o0 = gelu_exact(o0 + bv.x);
                    o1 = gelu_exact(o1 + bv.y);
                    store2h(Ch, idx, o0, o1);
                } else if (EPI == EPI_YBG) {
                    float2 bv = *(const float2*)&aux[col];
                    o0 += bv.x; o1 += bv.y;
                    *(float2*)&C0[idx] = make_float2(o0, o1);
                    store2h(Ch, idx, o0, o1);
                } else if (EPI == EPI_ZSUB) {               // z = b - acc
                    float2 av = *(const float2*)&aux[idx];
                    *(float2*)&C0[idx] = make_float2(av.x - o0, av.y - o1);
                } else if (EPI == EPI_RSUB) {               // r = acc - z (fp16 out)
                    float2 av = *(const float2*)&aux[idx];
                    store2h(Ch, idx, o0 - av.x, o1 - av.y);
                } else if (EPI == EPI_FISTA) {
                    float2 vv = *(const float2*)&aux[idx];   // v (fp32)
                    float u0 = vv.x - eta * o0, u1 = vv.y - eta * o1;
                    float a0n = copysignf(fmaxf(fabsf(u0) - thr, 0.0f), u0);
                    float a1n = copysignf(fmaxf(fabsf(u1) - thr, 0.0f), u1);
                    if (vout) {
                        float2 ao = *(const float2*)&aux2[idx];  // alpha_old
                        float v0 = a0n + beta * (a0n - ao.x);
                        float v1 = a1n + beta * (a1n - ao.y);
                        *(float2*)&C0[idx]   = make_float2(a0n, a1n);
                        *(float2*)&vout[idx] = make_float2(v0, v1);
                        store2h(vho, idx, v0, v1);
                    } else {
                        *(float2*)&C0[idx] = make_float2(a0n, a1n);
                        store2h(Ch, idx, a0n, a1n);
                    }
                } else {                                    // EPI_ADD
                    float2 yv = *(const float2*)&aux[idx];
                    *(float2*)&C0[idx] = make_float2(o0 + yv.x, o1 + yv.y);
                }
            }
        }
    }
}

// ---------------- prep kernels ------------------------------------------------
__global__ void round_kernel(const float4* __restrict__ s, fp16* __restrict__ o, int n4)
{
    int i = blockIdx.x * blockDim.x + threadIdx.x;
    if (i < n4) {
        float4 v = s[i];
        size_t idx = (size_t)i * 4;
        *(__half2*)(o + idx)     = __halves2half2(__float2half_rn(v.x), __float2half_rn(v.y));
        *(__half2*)(o + idx + 2) = __halves2half2(__float2half_rn(v.z), __float2half_rn(v.w));
    }
}

// transpose + round: src [R,C] fp32 -> dst [C,R] fp16
__global__ void tround_kernel(const float* __restrict__ s, fp16* __restrict__ o,
                              int R, int C)
{
    __shared__ float t[32][33];
    const int bx = blockIdx.x * 32;   // C offset
    const int by = blockIdx.y * 32;   // R offset
    const int x = threadIdx.x, y = threadIdx.y;
#pragma unroll
    for (int i = 0; i < 4; i++)
        t[y + i * 8][x] = s[(size_t)(by + y + i * 8) * C + bx + x];
    __syncthreads();
#pragma unroll
    for (int i = 0; i < 4; i++)
        o[(size_t)(bx + y + i * 8) * R + by + x] = __float2half_rn(t[x][y + i * 8]);
}

__global__ void fill0_kernel(float4* __restrict__ p, int n4)
{
    int i = blockIdx.x * blockDim.x + threadIdx.x;
    if (i < n4) p[i] = make_float4(0.f, 0.f, 0.f, 0.f);
}

// ---------------------------------------------------------------------------
extern "C" void kernel_launch(void* const* d_in, const int* in_sizes, int n_in,
                              void* d_out, int out_size)
{
    const float* x    = (const float*)d_in[0];
    const float* bvec = (const float*)d_in[1];
    const float* W1   = (const float*)d_in[2];
    const float* b1   = (const float*)d_in[3];
    const float* W2   = (const float*)d_in[4];
    const float* b2   = (const float*)d_in[5];
    const float* W3   = (const float*)d_in[6];
    const float* b3   = (const float*)d_in[7];
    const float* A    = (const float*)d_in[8];
    const float* leta = (const float*)d_in[9];
    const float* ltau = (const float*)d_in[10];
    const float* Psi  = (const float*)d_in[11];
    const float* Mmat = (const float*)d_in[12];

    float* out     = (float*)d_out;
    float* o_ybg   = out;
    float* o_z     = o_ybg   + (size_t)BATCH * NOUTD;
    float* o_alpha = o_z     + (size_t)BATCH * MMDIM;
    float* o_yhat  = o_alpha + (size_t)BATCH * NCODE;

#define SYM(p, s) void* p##_; cudaGetSymbolAddress(&p##_, s); auto* p = (decltype(&s[0]))p##_
    SYM(vbuf, g_v);  SYM(abuf, g_a0);
    SYM(xs, g_xs);   SYM(h1, g_h1);   SYM(h2, g_h2);   SYM(yb, g_yb);
    SYM(vs, g_vs);   SYM(rs, g_rs);   SYM(ap, g_ap);
    SYM(w1, g_w1);   SYM(w2, g_w2);   SYM(w3, g_w3);
    SYM(mw, g_m);    SYM(aa, g_aa);   SYM(at, g_at);   SYM(ps, g_ps);
#undef SYM

    cudaFuncSetAttribute((void*)wgemm<EPI_GELU>,  cudaFuncAttributeMaxDynamicSharedMemorySize, SMEM_BYTES);
    cudaFuncSetAttribute((void*)wgemm<EPI_YBG>,   cudaFuncAttributeMaxDynamicSharedMemorySize, SMEM_BYTES);
    cudaFuncSetAttribute((void*)wgemm<EPI_ZSUB>,  cudaFuncAttributeMaxDynamicSharedMemorySize, SMEM_BYTES);
    cudaFuncSetAttribute((void*)wgemm<EPI_RSUB>,  cudaFuncAttributeMaxDynamicSharedMemorySize, SMEM_BYTES);
    cudaFuncSetAttribute((void*)wgemm<EPI_FISTA>, cudaFuncAttributeMaxDynamicSharedMemorySize, SMEM_BYTES);
    cudaFuncSetAttribute((void*)wgemm<EPI_ADD>,   cudaFuncAttributeMaxDynamicSharedMemorySize, SMEM_BYTES);

    // host-side FISTA momentum (data-independent)
    float betas[KSTEPS + 1];
    {
        float t = 1.0f; betas[0] = 0.0f;
        for (int k = 1; k <= KSTEPS; k++) {
            float tn = 0.5f * (1.0f + sqrtf(1.0f + 4.0f * t * t));
            betas[k] = (t - 1.0f) / tn;
            t = tn;
        }
    }

    // ---- prep -----------------------------------------------------------------
    auto rounds = [&](const float* s, fp16* o, size_t n) {
        int n4 = (int)(n / 4);
        round_kernel<<<(n4 + 255) / 256, 256>>>((const float4*)s, o, n4);
    };
    rounds(x,    xs, (size_t)BATCH * PDIM);
    rounds(A,    aa, (size_t)MMDIM * NCODE);
    rounds(Mmat, mw, (size_t)MMDIM * NOUTD);
    rounds(Psi,  ps, (size_t)NOUTD * NCODE);
    tround_kernel<<<dim3(H1DIM / 32, PDIM / 32),  dim3(32, 8)>>>(W1, w1, PDIM,  H1DIM);
    tround_kernel<<<dim3(H2DIM / 32, H1DIM / 32), dim3(32, 8)>>>(W2, w2, H1DIM, H2DIM);
    tround_kernel<<<dim3(NOUTD / 32, H2DIM / 32), dim3(32, 8)>>>(W3, w3, H2DIM, NOUTD);
    tround_kernel<<<dim3(NCODE / 32, MMDIM / 32), dim3(32, 8)>>>(A,  at, MMDIM, NCODE);

    const int nA = BATCH * NCODE;
    fill0_kernel<<<(nA / 4 + 255) / 256, 256>>>((float4*)vbuf, nA / 4);
    fill0_kernel<<<(nA / 4 + 255) / 256, 256>>>((float4*)abuf, nA / 4);
    fill0_kernel<<<(nA / 8 + 255) / 256, 256>>>((float4*)vs, nA / 8);

    const dim3 blk(256);
#define GRID(N) dim3((N) / 128, BATCH / 128)

    // ---- background MLP -----------------------------------------------------
    wgemm<EPI_GELU><<<GRID(H1DIM), blk, SMEM_BYTES>>>(
        xs, w1, H1DIM, PDIM, nullptr, h1,
        b1, nullptr, nullptr, nullptr, nullptr, nullptr, 0, 0.f);
    wgemm<EPI_GELU><<<GRID(H2DIM), blk, SMEM_BYTES>>>(
        h1, w2, H2DIM, H1DIM, nullptr, h2,
        b2, nullptr, nullptr, nullptr, nullptr, nullptr, 0, 0.f);
    wgemm<EPI_YBG><<<GRID(NOUTD), blk, SMEM_BYTES>>>(
        h2, w3, NOUTD, H2DIM, o_ybg, yb,
        b3, nullptr, nullptr, nullptr, nullptr, nullptr, 0, 0.f);

    // ---- z = b - y_bg @ M^T --------------------------------------------------
    wgemm<EPI_ZSUB><<<GRID(MMDIM), blk, SMEM_BYTES>>>(
        yb, mw, MMDIM, NOUTD, o_z, nullptr,
        bvec, nullptr, nullptr, nullptr, nullptr, nullptr, 0, 0.f);

    // ---- FISTA loop (v-momentum fused into EPI_FISTA epilogue) ---------------
    for (int k = 0; k < KSTEPS; k++) {
        // r = v @ A^T - z  (fp16 out)
        wgemm<EPI_RSUB><<<GRID(MMDIM), blk, SMEM_BYTES>>>(
            vs, aa, MMDIM, NCODE, nullptr, rs,
            o_z, nullptr, nullptr, nullptr, nullptr, nullptr, 0, 0.f);
        // alpha_new = soft(v - eta*(r @ A), eta*tau);  v_next fused
        if (k < KSTEPS - 1) {
            wgemm<EPI_FISTA><<<GRID(NCODE), blk, SMEM_BYTES>>>(
                rs, at, NCODE, MMDIM, abuf, nullptr,
                vbuf, abuf, vbuf, vs, leta, ltau, k, betas[k + 1]);
        } else {
            wgemm<EPI_FISTA><<<GRID(NCODE), blk, SMEM_BYTES>>>(
                rs, at, NCODE, MMDIM, o_alpha, ap,
                vbuf, abuf, nullptr, nullptr, leta, ltau, k, 0.f);
        }
    }

    // ---- y_hat = y_bg + alpha @ Psi^T ----------------------------------------
    wgemm<EPI_ADD><<<GRID(NOUTD), blk, SMEM_BYTES>>>(
        ap, ps, NOUTD, NCODE, o_yhat, nullptr,
        o_ybg, nullptr, nullptr, nullptr, nullptr, nullptr, 0, 0.f);
}